// round 3
// baseline (speedup 1.0000x reference)
#include <cuda_runtime.h>
#include <cstdint>

// Problem dims (fixed for this problem instance)
#define Bb 32
#define Cc 256
#define Hh 36
#define Ww 64
#define Nn 4096
#define Kk (Hh * Ww)   // 2304

// Scratch: Gaussian masks, tf32-rounded fp32, [n, HW] row-major. 37.75 MB.
__device__ float g_G[(size_t)Nn * Kk];

__device__ __forceinline__ uint32_t f32_to_tf32(float x) {
    uint32_t u;
    asm("cvt.rna.tf32.f32 %0, %1;" : "=r"(u) : "f"(x));
    return u;
}

__device__ __forceinline__ void mma_tf32(float d[4], const uint32_t a[4], const uint32_t b[2]) {
    asm volatile(
        "mma.sync.aligned.m16n8k8.row.col.f32.tf32.tf32.f32 "
        "{%0,%1,%2,%3}, {%4,%5,%6,%7}, {%8,%9}, {%0,%1,%2,%3};\n"
        : "+f"(d[0]), "+f"(d[1]), "+f"(d[2]), "+f"(d[3])
        : "r"(a[0]), "r"(a[1]), "r"(a[2]), "r"(a[3]),
          "r"(b[0]), "r"(b[1]));
}

// ---------------------------------------------------------------------------
// Kernel 1: compute G[n, h*W+w] = exp(-A/denom), tf32-rounded.
// ---------------------------------------------------------------------------
__global__ void gauss_kernel(const float* __restrict__ mu,
                             const float* __restrict__ logsx,
                             const float* __restrict__ logsy,
                             const float* __restrict__ rho) {
    const int n = blockIdx.x;
    const float mux = mu[2 * n];
    const float muy = mu[2 * n + 1];
    const float sx = expf(logsx[n]) + 1e-6f;
    const float sy = expf(logsy[n]) + 1e-6f;
    const float r  = tanhf(rho[n]);
    const float isx = 1.0f / sx;
    const float isy = 1.0f / sy;
    const float iden = 1.0f / (2.0f * (1.0f - r * r + 1e-6f));
    float* Grow = g_G + (size_t)n * Kk;
    for (int k = threadIdx.x; k < Kk; k += blockDim.x) {
        const int h = k / Ww;
        const int w = k - h * Ww;
        const float x = -1.0f + w * (2.0f / (Ww - 1));
        const float y = -1.0f + h * (2.0f / (Hh - 1));
        const float xc = (x - mux) * isx;
        const float yc = (y - muy) * isy;
        const float A = xc * xc + yc * yc - 2.0f * r * xc * yc;
        Grow[k] = __uint_as_float(f32_to_tf32(expf(-A * iden)));
    }
}

// ---------------------------------------------------------------------------
// Kernel 2: per-batch GEMM pooled = G (n x K) * feat[b]^T (K x C), tf32 MMA,
// fused epilogue out[b,n] += sum_c pooled[n,c] * weight[n,c].
// ---------------------------------------------------------------------------
#define BM 128
#define BN 128
#define BK 16
#define AST (BK + 4)    // 20 floats  -> conflict-free A LDS
#define BST (BN + 8)    // 136 floats

// XOR swizzle on B columns: keeps both STS (k varies per lane) and LDS
// (t4 varies per lane) conflict-free with BST=136.
__device__ __forceinline__ int bswz(int k, int c) {
    return c ^ (((k >> 2) & 3) << 3);
}

__global__ __launch_bounds__(256)
void gemm_kernel(const float* __restrict__ feat,
                 const float* __restrict__ weight,
                 float* __restrict__ out) {
    __shared__ float As[2][BM][AST];
    __shared__ float Bs[2][BK][BST];

    const int n0 = blockIdx.x * BM;
    const int c0 = blockIdx.y * BN;
    const int b  = blockIdx.z;

    const int t    = threadIdx.x;
    const int lane = t & 31;
    const int wid  = t >> 5;
    const int g    = lane >> 2;   // groupID
    const int t4   = lane & 3;    // threadID_in_group
    const int wm   = wid & 1;     // warp m index (0..1): 64 rows each
    const int wn   = wid >> 1;    // warp n index (0..3): 32 cols each

    const int lr = t >> 2;        // 0..63  (row for gmem loads)
    const int lk = (t & 3) << 2;  // 0,4,8,12

    const float* gA0 = g_G + (size_t)(n0 + lr) * Kk + lk;
    const float* gA1 = g_G + (size_t)(n0 + lr + 64) * Kk + lk;
    const float* gB0 = feat + ((size_t)b * Cc + c0 + lr) * Kk + lk;
    const float* gB1 = feat + ((size_t)b * Cc + c0 + lr + 64) * Kk + lk;

    float acc[4][4][4];
    #pragma unroll
    for (int i = 0; i < 4; i++)
        #pragma unroll
        for (int j = 0; j < 4; j++)
            #pragma unroll
            for (int q = 0; q < 4; q++) acc[i][j][q] = 0.0f;

    float4 ra0 = *(const float4*)(gA0);
    float4 ra1 = *(const float4*)(gA1);
    float4 rb0 = *(const float4*)(gB0);
    float4 rb1 = *(const float4*)(gB1);

    // stage tile 0 into buffer 0 (feat tf32-rounded on the fly)
    *(float4*)&As[0][lr][lk]      = ra0;
    *(float4*)&As[0][lr + 64][lk] = ra1;
    Bs[0][lk + 0][bswz(lk + 0, lr)] = __uint_as_float(f32_to_tf32(rb0.x));
    Bs[0][lk + 1][bswz(lk + 1, lr)] = __uint_as_float(f32_to_tf32(rb0.y));
    Bs[0][lk + 2][bswz(lk + 2, lr)] = __uint_as_float(f32_to_tf32(rb0.z));
    Bs[0][lk + 3][bswz(lk + 3, lr)] = __uint_as_float(f32_to_tf32(rb0.w));
    Bs[0][lk + 0][bswz(lk + 0, lr + 64)] = __uint_as_float(f32_to_tf32(rb1.x));
    Bs[0][lk + 1][bswz(lk + 1, lr + 64)] = __uint_as_float(f32_to_tf32(rb1.y));
    Bs[0][lk + 2][bswz(lk + 2, lr + 64)] = __uint_as_float(f32_to_tf32(rb1.z));
    Bs[0][lk + 3][bswz(lk + 3, lr + 64)] = __uint_as_float(f32_to_tf32(rb1.w));
    __syncthreads();

    int buf = 0;
    #pragma unroll 1
    for (int k0 = 0; k0 < Kk; k0 += BK) {
        const bool has_next = (k0 + BK) < Kk;
        if (has_next) {
            ra0 = *(const float4*)(gA0 + k0 + BK);
            ra1 = *(const float4*)(gA1 + k0 + BK);
            rb0 = *(const float4*)(gB0 + k0 + BK);
            rb1 = *(const float4*)(gB1 + k0 + BK);
        }
        #pragma unroll
        for (int kk = 0; kk < BK; kk += 8) {
            uint32_t afr[4][4];
            uint32_t bfr[4][2];
            #pragma unroll
            for (int mf = 0; mf < 4; mf++) {
                const int row = wm * 64 + mf * 16 + g;
                afr[mf][0] = __float_as_uint(As[buf][row][kk + t4]);
                afr[mf][1] = __float_as_uint(As[buf][row + 8][kk + t4]);
                afr[mf][2] = __float_as_uint(As[buf][row][kk + t4 + 4]);
                afr[mf][3] = __float_as_uint(As[buf][row + 8][kk + t4 + 4]);
            }
            #pragma unroll
            for (int nf = 0; nf < 4; nf++) {
                const int col = wn * 32 + nf * 8 + g;
                bfr[nf][0] = __float_as_uint(Bs[buf][kk + t4][bswz(kk + t4, col)]);
                bfr[nf][1] = __float_as_uint(Bs[buf][kk + t4 + 4][bswz(kk + t4 + 4, col)]);
            }
            #pragma unroll
            for (int mf = 0; mf < 4; mf++)
                #pragma unroll
                for (int nf = 0; nf < 4; nf++)
                    mma_tf32(acc[mf][nf], afr[mf], bfr[nf]);
        }
        if (has_next) {
            const int nb = buf ^ 1;
            *(float4*)&As[nb][lr][lk]      = ra0;
            *(float4*)&As[nb][lr + 64][lk] = ra1;
            Bs[nb][lk + 0][bswz(lk + 0, lr)] = __uint_as_float(f32_to_tf32(rb0.x));
            Bs[nb][lk + 1][bswz(lk + 1, lr)] = __uint_as_float(f32_to_tf32(rb0.y));
            Bs[nb][lk + 2][bswz(lk + 2, lr)] = __uint_as_float(f32_to_tf32(rb0.z));
            Bs[nb][lk + 3][bswz(lk + 3, lr)] = __uint_as_float(f32_to_tf32(rb0.w));
            Bs[nb][lk + 0][bswz(lk + 0, lr + 64)] = __uint_as_float(f32_to_tf32(rb1.x));
            Bs[nb][lk + 1][bswz(lk + 1, lr + 64)] = __uint_as_float(f32_to_tf32(rb1.y));
            Bs[nb][lk + 2][bswz(lk + 2, lr + 64)] = __uint_as_float(f32_to_tf32(rb1.z));
            Bs[nb][lk + 3][bswz(lk + 3, lr + 64)] = __uint_as_float(f32_to_tf32(rb1.w));
            __syncthreads();
            buf = nb;
        }
    }

    // Fused epilogue: out[b, n] += sum_c pooled[n, c] * weight[n, c]
    #pragma unroll
    for (int mf = 0; mf < 4; mf++) {
        const int r0 = wm * 64 + mf * 16 + g;
        const int r1 = r0 + 8;
        float p0 = 0.0f, p1 = 0.0f;
        #pragma unroll
        for (int nf = 0; nf < 4; nf++) {
            const int cg = c0 + wn * 32 + nf * 8 + (t4 << 1);
            const float* w0 = weight + (size_t)(n0 + r0) * Cc + cg;
            const float* w1 = weight + (size_t)(n0 + r1) * Cc + cg;
            p0 += acc[mf][nf][0] * w0[0] + acc[mf][nf][1] * w0[1];
            p1 += acc[mf][nf][2] * w1[0] + acc[mf][nf][3] * w1[1];
        }
        p0 += __shfl_xor_sync(0xffffffffu, p0, 1);
        p0 += __shfl_xor_sync(0xffffffffu, p0, 2);
        p1 += __shfl_xor_sync(0xffffffffu, p1, 1);
        p1 += __shfl_xor_sync(0xffffffffu, p1, 2);
        if (t4 == 0) {
            atomicAdd(out + (size_t)b * Nn + n0 + r0, p0);
            atomicAdd(out + (size_t)b * Nn + n0 + r1, p1);
        }
    }
}

// ---------------------------------------------------------------------------
extern "C" void kernel_launch(void* const* d_in, const int* in_sizes, int n_in,
                              void* d_out, int out_size) {
    const float* feat   = (const float*)d_in[0];
    const float* mu     = (const float*)d_in[1];
    const float* logsx  = (const float*)d_in[2];
    const float* logsy  = (const float*)d_in[3];
    const float* rho    = (const float*)d_in[4];
    const float* weight = (const float*)d_in[5];
    float* out = (float*)d_out;

    cudaMemsetAsync(out, 0, (size_t)out_size * sizeof(float));
    gauss_kernel<<<Nn, 256>>>(mu, logsx, logsy, rho);
    dim3 grid(Nn / BM, Cc / BN, Bb);
    gemm_kernel<<<grid, 256>>>(feat, weight, out);
}

// round 4
// speedup vs baseline: 1.0015x; 1.0015x over previous
#include <cuda_runtime.h>
#include <cstdint>

// Problem dims (fixed for this problem instance)
#define Bb 32
#define Cc 256
#define Hh 36
#define Ww 64
#define Nn 4096
#define Kk (Hh * Ww)   // 2304

// Scratch: Gaussian masks, tf32-rounded fp32, [n, HW] row-major. 37.75 MB.
__device__ float g_G[(size_t)Nn * Kk];

__device__ __forceinline__ uint32_t f32_to_tf32(float x) {
    uint32_t u;
    asm("cvt.rna.tf32.f32 %0, %1;" : "=r"(u) : "f"(x));
    return u;
}

__device__ __forceinline__ void mma_tf32(float d[4], const uint32_t a[4], const uint32_t b[2]) {
    asm volatile(
        "mma.sync.aligned.m16n8k8.row.col.f32.tf32.tf32.f32 "
        "{%0,%1,%2,%3}, {%4,%5,%6,%7}, {%8,%9}, {%0,%1,%2,%3};\n"
        : "+f"(d[0]), "+f"(d[1]), "+f"(d[2]), "+f"(d[3])
        : "r"(a[0]), "r"(a[1]), "r"(a[2]), "r"(a[3]),
          "r"(b[0]), "r"(b[1]));
}

// ---------------------------------------------------------------------------
// Kernel 1: compute G[n, h*W+w] = exp(-A/denom), tf32-rounded.
// ---------------------------------------------------------------------------
__global__ void gauss_kernel(const float* __restrict__ mu,
                             const float* __restrict__ logsx,
                             const float* __restrict__ logsy,
                             const float* __restrict__ rho) {
    const int n = blockIdx.x;
    const float mux = mu[2 * n];
    const float muy = mu[2 * n + 1];
    const float sx = expf(logsx[n]) + 1e-6f;
    const float sy = expf(logsy[n]) + 1e-6f;
    const float r  = tanhf(rho[n]);
    const float isx = 1.0f / sx;
    const float isy = 1.0f / sy;
    const float iden = 1.0f / (2.0f * (1.0f - r * r + 1e-6f));
    float* Grow = g_G + (size_t)n * Kk;
    for (int k = threadIdx.x; k < Kk; k += blockDim.x) {
        const int h = k / Ww;
        const int w = k - h * Ww;
        const float x = -1.0f + w * (2.0f / (Ww - 1));
        const float y = -1.0f + h * (2.0f / (Hh - 1));
        const float xc = (x - mux) * isx;
        const float yc = (y - muy) * isy;
        const float A = xc * xc + yc * yc - 2.0f * r * xc * yc;
        Grow[k] = __uint_as_float(f32_to_tf32(expf(-A * iden)));
    }
}

// ---------------------------------------------------------------------------
// Kernel 2: per-batch GEMM pooled = G (n x K) * feat[b]^T (K x C), tf32 MMA,
// fused epilogue out[b,n] += sum_c pooled[n,c] * weight[n,c].
// ---------------------------------------------------------------------------
#define BM 128
#define BN 128
#define BK 16
#define AST (BK + 4)    // 20 floats  -> conflict-free A LDS
#define BST (BN + 8)    // 136 floats

// XOR swizzle on B columns: keeps both STS (k varies per lane) and LDS
// (t4 varies per lane) conflict-free with BST=136.
__device__ __forceinline__ int bswz(int k, int c) {
    return c ^ (((k >> 2) & 3) << 3);
}

__global__ __launch_bounds__(256)
void gemm_kernel(const float* __restrict__ feat,
                 const float* __restrict__ weight,
                 float* __restrict__ out) {
    __shared__ float As[2][BM][AST];
    __shared__ float Bs[2][BK][BST];

    const int n0 = blockIdx.x * BM;
    const int c0 = blockIdx.y * BN;
    const int b  = blockIdx.z;

    const int t    = threadIdx.x;
    const int lane = t & 31;
    const int wid  = t >> 5;
    const int g    = lane >> 2;   // groupID
    const int t4   = lane & 3;    // threadID_in_group
    const int wm   = wid & 1;     // warp m index (0..1): 64 rows each
    const int wn   = wid >> 1;    // warp n index (0..3): 32 cols each

    const int lr = t >> 2;        // 0..63  (row for gmem loads)
    const int lk = (t & 3) << 2;  // 0,4,8,12

    const float* gA0 = g_G + (size_t)(n0 + lr) * Kk + lk;
    const float* gA1 = g_G + (size_t)(n0 + lr + 64) * Kk + lk;
    const float* gB0 = feat + ((size_t)b * Cc + c0 + lr) * Kk + lk;
    const float* gB1 = feat + ((size_t)b * Cc + c0 + lr + 64) * Kk + lk;

    float acc[4][4][4];
    #pragma unroll
    for (int i = 0; i < 4; i++)
        #pragma unroll
        for (int j = 0; j < 4; j++)
            #pragma unroll
            for (int q = 0; q < 4; q++) acc[i][j][q] = 0.0f;

    float4 ra0 = *(const float4*)(gA0);
    float4 ra1 = *(const float4*)(gA1);
    float4 rb0 = *(const float4*)(gB0);
    float4 rb1 = *(const float4*)(gB1);

    // stage tile 0 into buffer 0 (feat tf32-rounded on the fly)
    *(float4*)&As[0][lr][lk]      = ra0;
    *(float4*)&As[0][lr + 64][lk] = ra1;
    Bs[0][lk + 0][bswz(lk + 0, lr)] = __uint_as_float(f32_to_tf32(rb0.x));
    Bs[0][lk + 1][bswz(lk + 1, lr)] = __uint_as_float(f32_to_tf32(rb0.y));
    Bs[0][lk + 2][bswz(lk + 2, lr)] = __uint_as_float(f32_to_tf32(rb0.z));
    Bs[0][lk + 3][bswz(lk + 3, lr)] = __uint_as_float(f32_to_tf32(rb0.w));
    Bs[0][lk + 0][bswz(lk + 0, lr + 64)] = __uint_as_float(f32_to_tf32(rb1.x));
    Bs[0][lk + 1][bswz(lk + 1, lr + 64)] = __uint_as_float(f32_to_tf32(rb1.y));
    Bs[0][lk + 2][bswz(lk + 2, lr + 64)] = __uint_as_float(f32_to_tf32(rb1.z));
    Bs[0][lk + 3][bswz(lk + 3, lr + 64)] = __uint_as_float(f32_to_tf32(rb1.w));
    __syncthreads();

    int buf = 0;
    #pragma unroll 1
    for (int k0 = 0; k0 < Kk; k0 += BK) {
        const bool has_next = (k0 + BK) < Kk;
        if (has_next) {
            ra0 = *(const float4*)(gA0 + k0 + BK);
            ra1 = *(const float4*)(gA1 + k0 + BK);
            rb0 = *(const float4*)(gB0 + k0 + BK);
            rb1 = *(const float4*)(gB1 + k0 + BK);
        }
        #pragma unroll
        for (int kk = 0; kk < BK; kk += 8) {
            uint32_t afr[4][4];
            uint32_t bfr[4][2];
            #pragma unroll
            for (int mf = 0; mf < 4; mf++) {
                const int row = wm * 64 + mf * 16 + g;
                afr[mf][0] = __float_as_uint(As[buf][row][kk + t4]);
                afr[mf][1] = __float_as_uint(As[buf][row + 8][kk + t4]);
                afr[mf][2] = __float_as_uint(As[buf][row][kk + t4 + 4]);
                afr[mf][3] = __float_as_uint(As[buf][row + 8][kk + t4 + 4]);
            }
            #pragma unroll
            for (int nf = 0; nf < 4; nf++) {
                const int col = wn * 32 + nf * 8 + g;
                bfr[nf][0] = __float_as_uint(Bs[buf][kk + t4][bswz(kk + t4, col)]);
                bfr[nf][1] = __float_as_uint(Bs[buf][kk + t4 + 4][bswz(kk + t4 + 4, col)]);
            }
            #pragma unroll
            for (int mf = 0; mf < 4; mf++)
                #pragma unroll
                for (int nf = 0; nf < 4; nf++)
                    mma_tf32(acc[mf][nf], afr[mf], bfr[nf]);
        }
        if (has_next) {
            const int nb = buf ^ 1;
            *(float4*)&As[nb][lr][lk]      = ra0;
            *(float4*)&As[nb][lr + 64][lk] = ra1;
            Bs[nb][lk + 0][bswz(lk + 0, lr)] = __uint_as_float(f32_to_tf32(rb0.x));
            Bs[nb][lk + 1][bswz(lk + 1, lr)] = __uint_as_float(f32_to_tf32(rb0.y));
            Bs[nb][lk + 2][bswz(lk + 2, lr)] = __uint_as_float(f32_to_tf32(rb0.z));
            Bs[nb][lk + 3][bswz(lk + 3, lr)] = __uint_as_float(f32_to_tf32(rb0.w));
            Bs[nb][lk + 0][bswz(lk + 0, lr + 64)] = __uint_as_float(f32_to_tf32(rb1.x));
            Bs[nb][lk + 1][bswz(lk + 1, lr + 64)] = __uint_as_float(f32_to_tf32(rb1.y));
            Bs[nb][lk + 2][bswz(lk + 2, lr + 64)] = __uint_as_float(f32_to_tf32(rb1.z));
            Bs[nb][lk + 3][bswz(lk + 3, lr + 64)] = __uint_as_float(f32_to_tf32(rb1.w));
            __syncthreads();
            buf = nb;
        }
    }

    // Fused epilogue: out[b, n] += sum_c pooled[n, c] * weight[n, c]
    #pragma unroll
    for (int mf = 0; mf < 4; mf++) {
        const int r0 = wm * 64 + mf * 16 + g;
        const int r1 = r0 + 8;
        float p0 = 0.0f, p1 = 0.0f;
        #pragma unroll
        for (int nf = 0; nf < 4; nf++) {
            const int cg = c0 + wn * 32 + nf * 8 + (t4 << 1);
            const float* w0 = weight + (size_t)(n0 + r0) * Cc + cg;
            const float* w1 = weight + (size_t)(n0 + r1) * Cc + cg;
            p0 += acc[mf][nf][0] * w0[0] + acc[mf][nf][1] * w0[1];
            p1 += acc[mf][nf][2] * w1[0] + acc[mf][nf][3] * w1[1];
        }
        p0 += __shfl_xor_sync(0xffffffffu, p0, 1);
        p0 += __shfl_xor_sync(0xffffffffu, p0, 2);
        p1 += __shfl_xor_sync(0xffffffffu, p1, 1);
        p1 += __shfl_xor_sync(0xffffffffu, p1, 2);
        if (t4 == 0) {
            atomicAdd(out + (size_t)b * Nn + n0 + r0, p0);
            atomicAdd(out + (size_t)b * Nn + n0 + r1, p1);
        }
    }
}

// ---------------------------------------------------------------------------
extern "C" void kernel_launch(void* const* d_in, const int* in_sizes, int n_in,
                              void* d_out, int out_size) {
    const float* feat   = (const float*)d_in[0];
    const float* mu     = (const float*)d_in[1];
    const float* logsx  = (const float*)d_in[2];
    const float* logsy  = (const float*)d_in[3];
    const float* rho    = (const float*)d_in[4];
    const float* weight = (const float*)d_in[5];
    float* out = (float*)d_out;

    cudaMemsetAsync(out, 0, (size_t)out_size * sizeof(float));
    gauss_kernel<<<Nn, 256>>>(mu, logsx, logsy, rho);
    dim3 grid(Nn / BM, Cc / BN, Bb);
    gemm_kernel<<<grid, 256>>>(feat, weight, out);
}

// round 6
// speedup vs baseline: 1.3056x; 1.3036x over previous
#include <cuda_runtime.h>
#include <cstdint>

// Problem dims (fixed)
#define Bb 32
#define Cc 256
#define Hh 36
#define Ww 64
#define Nn 4096
#define Kk 2304

// Scratch: G masks and tf32-rounded feat, both RNA-rounded fp32.
__device__ float g_G[(size_t)Nn * Kk];            // 37.75 MB, [n][k]
__device__ float g_F[(size_t)Bb * Cc * Kk];       // 75.5 MB,  [b][c][k]

__device__ __forceinline__ uint32_t f32_to_tf32(float x) {
    uint32_t u;
    asm("cvt.rna.tf32.f32 %0, %1;" : "=r"(u) : "f"(x));
    return u;
}
__device__ __forceinline__ uint32_t smem_u32(const void* p) {
    uint32_t a;
    asm("{ .reg .u64 t; cvta.to.shared.u64 t, %1; cvt.u32.u64 %0, t; }"
        : "=r"(a) : "l"(p));
    return a;
}
__device__ __forceinline__ void mma_tf32(float d[4], const uint32_t a[4], const uint32_t b[2]) {
    asm volatile(
        "mma.sync.aligned.m16n8k8.row.col.f32.tf32.tf32.f32 "
        "{%0,%1,%2,%3}, {%4,%5,%6,%7}, {%8,%9}, {%0,%1,%2,%3};\n"
        : "+f"(d[0]), "+f"(d[1]), "+f"(d[2]), "+f"(d[3])
        : "r"(a[0]), "r"(a[1]), "r"(a[2]), "r"(a[3]),
          "r"(b[0]), "r"(b[1]));
}
#define CP_ASYNC16(dst, src) \
    asm volatile("cp.async.cg.shared.global [%0], [%1], 16;" \
                 :: "r"((uint32_t)(dst)), "l"(src) : "memory")
#define CP_COMMIT() asm volatile("cp.async.commit_group;" ::: "memory")
#define CP_WAIT1()  asm volatile("cp.async.wait_group 1;" ::: "memory")
#define CP_WAIT0()  asm volatile("cp.async.wait_group 0;" ::: "memory")

// ---------------------------------------------------------------------------
// Kernel 0: round feat to tf32 (RNA) once.  18.87M floats, float4/thread.
// ---------------------------------------------------------------------------
__global__ void round_feat(const float* __restrict__ feat) {
    const size_t i = ((size_t)blockIdx.x * 256 + threadIdx.x) * 4;
    float4 v = *(const float4*)(feat + i);
    float4 o;
    o.x = __uint_as_float(f32_to_tf32(v.x));
    o.y = __uint_as_float(f32_to_tf32(v.y));
    o.z = __uint_as_float(f32_to_tf32(v.z));
    o.w = __uint_as_float(f32_to_tf32(v.w));
    *(float4*)(g_F + i) = o;
}

// ---------------------------------------------------------------------------
// Kernel 1: Gaussian masks, tf32(RNA)-rounded.
// ---------------------------------------------------------------------------
__global__ void gauss_kernel(const float* __restrict__ mu,
                             const float* __restrict__ logsx,
                             const float* __restrict__ logsy,
                             const float* __restrict__ rho) {
    const int n = blockIdx.x;
    const float mux = mu[2 * n];
    const float muy = mu[2 * n + 1];
    const float sx = expf(logsx[n]) + 1e-6f;
    const float sy = expf(logsy[n]) + 1e-6f;
    const float r  = tanhf(rho[n]);
    const float isx = 1.0f / sx;
    const float isy = 1.0f / sy;
    const float iden = 1.0f / (2.0f * (1.0f - r * r + 1e-6f));
    float* Grow = g_G + (size_t)n * Kk;
    for (int k = threadIdx.x; k < Kk; k += blockDim.x) {
        const int h = k / Ww;
        const int w = k - h * Ww;
        const float x = -1.0f + w * (2.0f / (Ww - 1));
        const float y = -1.0f + h * (2.0f / (Hh - 1));
        const float xc = (x - mux) * isx;
        const float yc = (y - muy) * isy;
        const float A = xc * xc + yc * yc - 2.0f * r * xc * yc;
        Grow[k] = __uint_as_float(f32_to_tf32(expf(-A * iden)));
    }
}

// ---------------------------------------------------------------------------
// Kernel 2: tf32 mma.sync GEMM.
//   CTA: 128 (n) x 256 (c, full C), K swept in BK=32 chunks, 3-stage cp.async.
//   8 warps as 2 (m) x 4 (n), warp tile 64x64.
//   Both tiles stored [row][36 floats] in smem: conflict-free LDS
//   (banks 36*g + t4 mod 32 cover all 32), cp.async 16B-aligned.
//   Fused epilogue: out[b,n] = sum_c D[n,c]*weight[n,c] via smem reduction.
// ---------------------------------------------------------------------------
#define BK 32
#define NIT (Kk / BK)            // 72
#define ROWST 36                 // floats per smem row (32 + 4 pad)
#define A_BYTES (128 * ROWST * 4)   // 18432
#define B_BYTES (256 * ROWST * 4)   // 36864
#define STAGE   (A_BYTES + B_BYTES) // 55296
#define NSTG 3
#define SMEM_DYN (NSTG * STAGE)     // 165888

__global__ __launch_bounds__(256, 1)
void gemm_mma(const float* __restrict__ weight, float* __restrict__ out) {
    extern __shared__ char smem[];
    __shared__ float red[4][128];
    const uint32_t sb = smem_u32(smem);

    const int tid  = threadIdx.x;
    const int lane = tid & 31;
    const int wid  = tid >> 5;
    const int g    = lane >> 2;
    const int t4   = lane & 3;
    const int wm   = wid & 1;    // 0..1 : 64-row half
    const int wn   = wid >> 1;   // 0..3 : 64-col quarter

    const int n0 = blockIdx.x * 128;
    const int b  = blockIdx.y;

    const char* srcA0 = (const char*)(g_G + (size_t)n0 * Kk);
    const char* srcF0 = (const char*)(g_F + (size_t)b * Cc * Kk);

    // issue one BK=32 stage: A 1024 granules + B 2048 granules, 12/thread
    const int arow = tid >> 3;          // reused below
    const int aq   = tid & 7;
    #define ISSUE_STAGE(ii, ss) do {                                          \
        const uint32_t stA = sb + (ss) * STAGE;                               \
        const uint32_t stB = stA + A_BYTES;                                   \
        const char* sA = srcA0 + (size_t)(ii) * (BK * 4);                     \
        const char* sB = srcF0 + (size_t)(ii) * (BK * 4);                     \
        _Pragma("unroll")                                                     \
        for (int j = 0; j < 4; j++) {                                         \
            const int r = arow + j * 32;                                      \
            CP_ASYNC16(stA + r * (ROWST * 4) + aq * 16,                       \
                       sA + (size_t)r * (Kk * 4) + aq * 16);                  \
        }                                                                     \
        _Pragma("unroll")                                                     \
        for (int j = 0; j < 8; j++) {                                         \
            const int c = arow + j * 32;                                      \
            CP_ASYNC16(stB + c * (ROWST * 4) + aq * 16,                       \
                       sB + (size_t)c * (Kk * 4) + aq * 16);                  \
        }                                                                     \
        CP_COMMIT();                                                          \
    } while (0)

    float acc[4][8][4];
    #pragma unroll
    for (int i = 0; i < 4; i++)
        #pragma unroll
        for (int j = 0; j < 8; j++)
            #pragma unroll
            for (int q = 0; q < 4; q++) acc[i][j][q] = 0.0f;

    ISSUE_STAGE(0, 0);
    ISSUE_STAGE(1, 1);

    int s = 0;
    #pragma unroll 1
    for (int i = 0; i < NIT; i++) {
        if (i == NIT - 1) { CP_WAIT0(); } else { CP_WAIT1(); }
        __syncthreads();
        if (i + 2 < NIT) {
            const int s2 = (s + 2 >= NSTG) ? (s + 2 - NSTG) : (s + 2);
            ISSUE_STAGE(i + 2, s2);
        }
        const float* As = (const float*)(smem + s * STAGE);
        const float* Bs = (const float*)(smem + s * STAGE + A_BYTES);

        #pragma unroll
        for (int kk = 0; kk < BK; kk += 8) {
            uint32_t afr[4][4];
            uint32_t bfr[8][2];
            #pragma unroll
            for (int mf = 0; mf < 4; mf++) {
                const int row = wm * 64 + mf * 16 + g;
                afr[mf][0] = __float_as_uint(As[row * ROWST + kk + t4]);
                afr[mf][1] = __float_as_uint(As[(row + 8) * ROWST + kk + t4]);
                afr[mf][2] = __float_as_uint(As[row * ROWST + kk + t4 + 4]);
                afr[mf][3] = __float_as_uint(As[(row + 8) * ROWST + kk + t4 + 4]);
            }
            #pragma unroll
            for (int nf = 0; nf < 8; nf++) {
                const int col = wn * 64 + nf * 8 + g;
                bfr[nf][0] = __float_as_uint(Bs[col * ROWST + kk + t4]);
                bfr[nf][1] = __float_as_uint(Bs[col * ROWST + kk + t4 + 4]);
            }
            #pragma unroll
            for (int mf = 0; mf < 4; mf++)
                #pragma unroll
                for (int nf = 0; nf < 8; nf++)
                    mma_tf32(acc[mf][nf], afr[mf], bfr[nf]);
        }
        s = (s + 1 >= NSTG) ? 0 : (s + 1);
    }

    // ---------------- epilogue: weight dot + cross-warp reduction ----------
    #pragma unroll
    for (int mf = 0; mf < 4; mf++) {
        const int r0 = wm * 64 + mf * 16 + g;
        const int r1 = r0 + 8;
        float p0 = 0.0f, p1 = 0.0f;
        #pragma unroll
        for (int nf = 0; nf < 8; nf++) {
            const int c = wn * 64 + nf * 8 + (t4 << 1);
            const float2 w0 = *(const float2*)(weight + (size_t)(n0 + r0) * Cc + c);
            const float2 w1 = *(const float2*)(weight + (size_t)(n0 + r1) * Cc + c);
            p0 += acc[mf][nf][0] * w0.x + acc[mf][nf][1] * w0.y;
            p1 += acc[mf][nf][2] * w1.x + acc[mf][nf][3] * w1.y;
        }
        p0 += __shfl_xor_sync(0xffffffffu, p0, 1);
        p0 += __shfl_xor_sync(0xffffffffu, p0, 2);
        p1 += __shfl_xor_sync(0xffffffffu, p1, 1);
        p1 += __shfl_xor_sync(0xffffffffu, p1, 2);
        if (t4 == 0) {
            red[wn][r0] = p0;
            red[wn][r1] = p1;
        }
    }
    __syncthreads();
    if (tid < 128) {
        const float v = red[0][tid] + red[1][tid] + red[2][tid] + red[3][tid];
        out[(size_t)b * Nn + n0 + tid] = v;
    }
}

// ---------------------------------------------------------------------------
extern "C" void kernel_launch(void* const* d_in, const int* in_sizes, int n_in,
                              void* d_out, int out_size) {
    const float* feat   = (const float*)d_in[0];
    const float* mu     = (const float*)d_in[1];
    const float* logsx  = (const float*)d_in[2];
    const float* logsy  = (const float*)d_in[3];
    const float* rho    = (const float*)d_in[4];
    const float* weight = (const float*)d_in[5];
    float* out = (float*)d_out;

    static bool attr_set = false;
    if (!attr_set) {
        cudaFuncSetAttribute(gemm_mma, cudaFuncAttributeMaxDynamicSharedMemorySize,
                             SMEM_DYN);
        attr_set = true;
    }

    round_feat<<<(Bb * Cc * Kk) / (256 * 4), 256>>>(feat);
    gauss_kernel<<<Nn, 256>>>(mu, logsx, logsy, rho);
    dim3 grid(Nn / 128, Bb);
    gemm_mma<<<grid, 256, SMEM_DYN>>>(weight, out);
}

// round 8
// speedup vs baseline: 2.2834x; 1.7489x over previous
#include <cuda_runtime.h>
#include <cuda_fp16.h>
#include <cstdint>

// Problem dims (fixed)
#define Bb 32
#define Cc 256
#define Hh 36
#define Ww 64
#define Nn 4096
#define Kk 2304

// Scratch: fp16 G masks [n][k] (18.9 MB) and fp16 feat [b][c][k] (37.7 MB)
__device__ __half g_G[(size_t)Nn * Kk];
__device__ __half g_F[(size_t)Bb * Cc * Kk];

__device__ __forceinline__ uint32_t smem_u32(const void* p) {
    uint32_t a;
    asm("{ .reg .u64 t; cvta.to.shared.u64 t, %1; cvt.u32.u64 %0, t; }"
        : "=r"(a) : "l"(p));
    return a;
}
__device__ __forceinline__ void mma_f16(float d[4], const uint32_t a[4], const uint32_t b0,
                                        const uint32_t b1) {
    asm volatile(
        "mma.sync.aligned.m16n8k16.row.col.f32.f16.f16.f32 "
        "{%0,%1,%2,%3}, {%4,%5,%6,%7}, {%8,%9}, {%0,%1,%2,%3};\n"
        : "+f"(d[0]), "+f"(d[1]), "+f"(d[2]), "+f"(d[3])
        : "r"(a[0]), "r"(a[1]), "r"(a[2]), "r"(a[3]), "r"(b0), "r"(b1));
}
#define LDSM4(r, addr) \
    asm volatile("ldmatrix.sync.aligned.m8n8.x4.shared.b16 {%0,%1,%2,%3}, [%4];" \
                 : "=r"((r)[0]), "=r"((r)[1]), "=r"((r)[2]), "=r"((r)[3]) \
                 : "r"(addr))
#define CP_ASYNC16(dst, src) \
    asm volatile("cp.async.cg.shared.global [%0], [%1], 16;" \
                 :: "r"((uint32_t)(dst)), "l"(src) : "memory")
#define CP_COMMIT() asm volatile("cp.async.commit_group;" ::: "memory")
#define CP_WAIT1()  asm volatile("cp.async.wait_group 1;" ::: "memory")
#define CP_WAIT0()  asm volatile("cp.async.wait_group 0;" ::: "memory")

// ---------------------------------------------------------------------------
// Kernel 0: feat (fp32) -> fp16 scratch. 8 floats / thread.
// ---------------------------------------------------------------------------
__global__ void feat_to_h(const float* __restrict__ feat) {
    const size_t i = ((size_t)blockIdx.x * 256 + threadIdx.x) * 8;
    const float4 v0 = *(const float4*)(feat + i);
    const float4 v1 = *(const float4*)(feat + i + 4);
    __half2 h[4];
    h[0] = __floats2half2_rn(v0.x, v0.y);
    h[1] = __floats2half2_rn(v0.z, v0.w);
    h[2] = __floats2half2_rn(v1.x, v1.y);
    h[3] = __floats2half2_rn(v1.z, v1.w);
    *(uint4*)(g_F + i) = *(const uint4*)h;
}

// ---------------------------------------------------------------------------
// Kernel 1: Gaussian masks -> fp16.
// ---------------------------------------------------------------------------
__global__ void gauss_kernel(const float* __restrict__ mu,
                             const float* __restrict__ logsx,
                             const float* __restrict__ logsy,
                             const float* __restrict__ rho) {
    const int n = blockIdx.x;
    const float mux = mu[2 * n];
    const float muy = mu[2 * n + 1];
    const float sx = expf(logsx[n]) + 1e-6f;
    const float sy = expf(logsy[n]) + 1e-6f;
    const float r  = tanhf(rho[n]);
    const float isx = 1.0f / sx;
    const float isy = 1.0f / sy;
    const float iden = 1.0f / (2.0f * (1.0f - r * r + 1e-6f));
    __half* Grow = g_G + (size_t)n * Kk;
    for (int k = threadIdx.x; k < Kk; k += blockDim.x) {
        const int h = k / Ww;
        const int w = k - h * Ww;
        const float x = -1.0f + w * (2.0f / (Ww - 1));
        const float y = -1.0f + h * (2.0f / (Hh - 1));
        const float xc = (x - mux) * isx;
        const float yc = (y - muy) * isy;
        const float A = xc * xc + yc * yc - 2.0f * r * xc * yc;
        Grow[k] = __float2half_rn(expf(-A * iden));
    }
}

// ---------------------------------------------------------------------------
// Kernel 2: fp16 mma.sync GEMM (fp32 accumulate).
//   CTA: 128 (n) x 256 (c, full C).  K in BK=64 chunks, 3-stage cp.async.
//   8 warps = 2 (m) x 4 (n), warp tile 64x64.  Fragments via ldmatrix.x4.
//   Both tiles K-major [row][64 halves], row stride 72 halves (144 B):
//   16B-aligned for cp.async, conflict-free for ldmatrix (banks 4*row mod 32).
//   ldmatrix.x4 register order: r0=(rows0-7,k0-7) r1=(rows8-15,k0-7)
//   r2=(rows0-7,k8-15) r3=(rows8-15,k8-15) -> B pairs are (r0,r2) and (r1,r3).
//   Fused epilogue: out[b,n] = sum_c D[n,c]*weight[n,c].
// ---------------------------------------------------------------------------
#define BK 64
#define NIT (Kk / BK)               // 36
#define ROWB 144                    // bytes per smem row (128 data + 16 pad)
#define A_BYTES (128 * ROWB)        // 18432
#define B_BYTES (256 * ROWB)        // 36864
#define STAGE   (A_BYTES + B_BYTES) // 55296
#define NSTG 3
#define SMEM_DYN (NSTG * STAGE)     // 165888

__global__ __launch_bounds__(256, 1)
void gemm_mma(const float* __restrict__ weight, float* __restrict__ out) {
    extern __shared__ char smem[];
    __shared__ float red[4][128];
    const uint32_t sb = smem_u32(smem);

    const int tid  = threadIdx.x;
    const int lane = tid & 31;
    const int wid  = tid >> 5;
    const int g    = lane >> 2;
    const int t4   = lane & 3;
    const int wm   = wid & 1;    // 0..1 : 64-row half (n)
    const int wn   = wid >> 1;   // 0..3 : 64-col quarter (c)

    const int n0 = blockIdx.x * 128;
    const int b  = blockIdx.y;

    const char* srcA0 = (const char*)(g_G + (size_t)n0 * Kk);
    const char* srcB0 = (const char*)(g_F + (size_t)b * Cc * Kk);

    // cp.async mapping: 3072 granules of 16B per stage, 12 per thread
    const int crow = tid >> 3;       // 0..31
    const int cq   = tid & 7;        // 0..7
    #define ISSUE_STAGE(ii, ss) do {                                          \
        const uint32_t stA = sb + (ss) * STAGE;                               \
        const uint32_t stB = stA + A_BYTES;                                   \
        const char* sA = srcA0 + (size_t)(ii) * (BK * 2);                     \
        const char* sB = srcB0 + (size_t)(ii) * (BK * 2);                     \
        _Pragma("unroll")                                                     \
        for (int j = 0; j < 4; j++) {                                         \
            const int r = crow + j * 32;                                      \
            CP_ASYNC16(stA + r * ROWB + cq * 16,                              \
                       sA + (size_t)r * (Kk * 2) + cq * 16);                  \
        }                                                                     \
        _Pragma("unroll")                                                     \
        for (int j = 0; j < 8; j++) {                                         \
            const int c = crow + j * 32;                                      \
            CP_ASYNC16(stB + c * ROWB + cq * 16,                              \
                       sB + (size_t)c * (Kk * 2) + cq * 16);                  \
        }                                                                     \
        CP_COMMIT();                                                          \
    } while (0)

    // ldmatrix per-thread base addresses:
    // lanes 0-15 -> rows 0-15 at k-byte 0; lanes 16-31 -> rows 0-15 at k-byte 16
    const int rin = (lane & 7) + ((lane >> 3) & 1) * 8;   // 0..15
    const int kof = (lane >> 4) * 16;                     // 0 or 16 bytes
    const uint32_t aBase = sb + (wm * 64 + rin) * ROWB + kof;
    const uint32_t bBase = sb + A_BYTES + (wn * 64 + rin) * ROWB + kof;

    float acc[4][8][4];
    #pragma unroll
    for (int i = 0; i < 4; i++)
        #pragma unroll
        for (int j = 0; j < 8; j++)
            #pragma unroll
            for (int q = 0; q < 4; q++) acc[i][j][q] = 0.0f;

    ISSUE_STAGE(0, 0);
    ISSUE_STAGE(1, 1);

    int s = 0;
    #pragma unroll 1
    for (int i = 0; i < NIT; i++) {
        if (i == NIT - 1) { CP_WAIT0(); } else { CP_WAIT1(); }
        __syncthreads();
        if (i + 2 < NIT) {
            const int s2 = (s + 2 >= NSTG) ? (s + 2 - NSTG) : (s + 2);
            ISSUE_STAGE(i + 2, s2);
        }
        const uint32_t aS = aBase + s * STAGE;
        const uint32_t bS = bBase + s * STAGE;

        #pragma unroll
        for (int kk = 0; kk < BK; kk += 16) {
            uint32_t afr[4][4], bfr[4][4];
            #pragma unroll
            for (int mf = 0; mf < 4; mf++)
                LDSM4(afr[mf], aS + mf * (16 * ROWB) + kk * 2);
            #pragma unroll
            for (int nf2 = 0; nf2 < 4; nf2++)
                LDSM4(bfr[nf2], bS + nf2 * (16 * ROWB) + kk * 2);
            // B register pairing: n-lo slice = (r0, r2), n-hi slice = (r1, r3)
            #pragma unroll
            for (int mf = 0; mf < 4; mf++)
                #pragma unroll
                for (int nf2 = 0; nf2 < 4; nf2++) {
                    mma_f16(acc[mf][nf2 * 2],     afr[mf], bfr[nf2][0], bfr[nf2][2]);
                    mma_f16(acc[mf][nf2 * 2 + 1], afr[mf], bfr[nf2][1], bfr[nf2][3]);
                }
        }
        s = (s + 1 >= NSTG) ? 0 : (s + 1);
    }

    // ---------------- epilogue: weight dot + cross-warp reduction ----------
    #pragma unroll
    for (int mf = 0; mf < 4; mf++) {
        const int r0 = wm * 64 + mf * 16 + g;
        const int r1 = r0 + 8;
        float p0 = 0.0f, p1 = 0.0f;
        #pragma unroll
        for (int nf = 0; nf < 8; nf++) {
            const int c = wn * 64 + nf * 8 + (t4 << 1);
            const float2 w0 = *(const float2*)(weight + (size_t)(n0 + r0) * Cc + c);
            const float2 w1 = *(const float2*)(weight + (size_t)(n0 + r1) * Cc + c);
            p0 += acc[mf][nf][0] * w0.x + acc[mf][nf][1] * w0.y;
            p1 += acc[mf][nf][2] * w1.x + acc[mf][nf][3] * w1.y;
        }
        p0 += __shfl_xor_sync(0xffffffffu, p0, 1);
        p0 += __shfl_xor_sync(0xffffffffu, p0, 2);
        p1 += __shfl_xor_sync(0xffffffffu, p1, 1);
        p1 += __shfl_xor_sync(0xffffffffu, p1, 2);
        if (t4 == 0) {
            red[wn][r0] = p0;
            red[wn][r1] = p1;
        }
    }
    __syncthreads();
    if (tid < 128) {
        const float v = red[0][tid] + red[1][tid] + red[2][tid] + red[3][tid];
        out[(size_t)b * Nn + n0 + tid] = v;
    }
}

// ---------------------------------------------------------------------------
extern "C" void kernel_launch(void* const* d_in, const int* in_sizes, int n_in,
                              void* d_out, int out_size) {
    const float* feat   = (const float*)d_in[0];
    const float* mu     = (const float*)d_in[1];
    const float* logsx  = (const float*)d_in[2];
    const float* logsy  = (const float*)d_in[3];
    const float* rho    = (const float*)d_in[4];
    const float* weight = (const float*)d_in[5];
    float* out = (float*)d_out;

    static bool attr_set = false;
    if (!attr_set) {
        cudaFuncSetAttribute(gemm_mma, cudaFuncAttributeMaxDynamicSharedMemorySize,
                             SMEM_DYN);
        attr_set = true;
    }

    feat_to_h<<<(Bb * Cc * Kk) / (256 * 8), 256>>>(feat);
    gauss_kernel<<<Nn, 256>>>(mu, logsx, logsy, rho);
    dim3 grid(Nn / 128, Bb);
    gemm_mma<<<grid, 256, SMEM_DYN>>>(weight, out);
}